// round 8
// baseline (speedup 1.0000x reference)
#include <cuda_runtime.h>
#include <cuda_bf16.h>

// DIST_loss: loss = sum_i ||preds_i - targets_i||_2 / (N+1)
// preds, targets: [N, 2] float32 (interleaved x,y). Output: 1 float.
//
// Single persistent-wave streaming reduction (HBM-bound):
//   - grid = 760 blocks (152 SMs x 5 blocks/SM = one wave at this footprint)
//   - 4x-unrolled grid-stride: 8 independent LDG.128 (__ldcs) per iteration
//   - sqrt.approx.f32 (single MUFU; ~1e-6/elem, cancels in the 16M-sum)
//   - warp+smem block reduce -> g_partials; integer-atomic last-block-done
//     final reduce in double (deterministic fixed order), resets counter.
// Allocation-free, graph-capturable (one launch), no float atomics.

#define GRID_BLOCKS 760
#define RED_THREADS 256

__device__ float g_partials[GRID_BLOCKS];
__device__ unsigned int g_count = 0;

__device__ __forceinline__ float fast_sqrt(float x)
{
    float r;
    asm("sqrt.approx.f32 %0, %1;" : "=f"(r) : "f"(x));
    return r;
}

__device__ __forceinline__ float pair_dist(float4 a, float4 b)
{
    float dx0 = a.x - b.x;
    float dy0 = a.y - b.y;
    float dx1 = a.z - b.z;
    float dy1 = a.w - b.w;
    return fast_sqrt(fmaf(dx0, dx0, dy0 * dy0)) +
           fast_sqrt(fmaf(dx1, dx1, dy1 * dy1));
}

__global__ __launch_bounds__(RED_THREADS, 5)
void dist_loss_kernel(const float4* __restrict__ preds4,
                      const float4* __restrict__ targs4,
                      int n4, int n_points,
                      float* __restrict__ out, float inv_np1)
{
    const int tid = blockIdx.x * blockDim.x + threadIdx.x;
    const int stride = gridDim.x * blockDim.x;

    float s0 = 0.0f, s1 = 0.0f, s2 = 0.0f, s3 = 0.0f;

    int i = tid;
    const int stride4 = stride * 4;
    for (; i + 3 * stride < n4; i += stride4) {
        float4 a0 = __ldcs(&preds4[i]);
        float4 a1 = __ldcs(&preds4[i + stride]);
        float4 a2 = __ldcs(&preds4[i + 2 * stride]);
        float4 a3 = __ldcs(&preds4[i + 3 * stride]);
        float4 b0 = __ldcs(&targs4[i]);
        float4 b1 = __ldcs(&targs4[i + stride]);
        float4 b2 = __ldcs(&targs4[i + 2 * stride]);
        float4 b3 = __ldcs(&targs4[i + 3 * stride]);

        s0 += pair_dist(a0, b0);
        s1 += pair_dist(a1, b1);
        s2 += pair_dist(a2, b2);
        s3 += pair_dist(a3, b3);
    }
    for (; i < n4; i += stride)
        s0 += pair_dist(__ldcs(&preds4[i]), __ldcs(&targs4[i]));

    float sum = (s0 + s1) + (s2 + s3);

    // Block reduce
    #pragma unroll
    for (int off = 16; off > 0; off >>= 1)
        sum += __shfl_down_sync(0xffffffffu, sum, off);

    __shared__ float wsum[RED_THREADS / 32];
    if ((threadIdx.x & 31) == 0)
        wsum[threadIdx.x >> 5] = sum;
    __syncthreads();

    __shared__ bool is_last;
    if (threadIdx.x < 32) {
        float v = (threadIdx.x < RED_THREADS / 32) ? wsum[threadIdx.x] : 0.0f;
        #pragma unroll
        for (int off = 4; off > 0; off >>= 1)
            v += __shfl_down_sync(0xffffffffu, v, off);
        if (threadIdx.x == 0) {
            g_partials[blockIdx.x] = v;
            __threadfence();
            unsigned int prev = atomicAdd(&g_count, 1u);
            is_last = (prev == gridDim.x - 1);
        }
    }
    __syncthreads();

    // Last block: deterministic final reduction in double (cold path).
    if (is_last) {
        double s = 0.0;
        const int nb = gridDim.x;
        for (int k = threadIdx.x; k < nb; k += RED_THREADS)
            s += (double)g_partials[k];

        // Odd trailing point (cold path, exact sqrt).
        if (threadIdx.x == 0 && (n_points & 1)) {
            const float2* p2 = (const float2*)preds4;
            const float2* t2 = (const float2*)targs4;
            float2 a = p2[n_points - 1];
            float2 b = t2[n_points - 1];
            float dx = a.x - b.x, dy = a.y - b.y;
            s += (double)sqrtf(fmaf(dx, dx, dy * dy));
        }

        #pragma unroll
        for (int off = 16; off > 0; off >>= 1)
            s += __shfl_down_sync(0xffffffffu, s, off);

        __shared__ double dsum[RED_THREADS / 32];
        if ((threadIdx.x & 31) == 0)
            dsum[threadIdx.x >> 5] = s;
        __syncthreads();

        if (threadIdx.x == 0) {
            double total = 0.0;
            #pragma unroll
            for (int w = 0; w < RED_THREADS / 32; w++)
                total += dsum[w];
            out[0] = (float)(total * (double)inv_np1);
            g_count = 0;  // reset for next graph replay
        }
    }
}

extern "C" void kernel_launch(void* const* d_in, const int* in_sizes, int n_in,
                              void* d_out, int out_size)
{
    const float4* preds4 = (const float4*)d_in[0];
    const float4* targs4 = (const float4*)d_in[1];
    float* out = (float*)d_out;

    const int total_f = in_sizes[0];     // 2 * N
    const int n_points = total_f / 2;    // N
    const int n4 = total_f / 4;          // float4 count (2 points each)

    int blocks = GRID_BLOCKS;            // defensive clamp (scratch bound)
    dist_loss_kernel<<<blocks, RED_THREADS>>>(
        preds4, targs4, n4, n_points, out,
        (float)(1.0 / (double)(n_points + 1)));
}